// round 1
// baseline (speedup 1.0000x reference)
#include <cuda_runtime.h>
#include <cuda_bf16.h>
#include <math.h>

#define V_SZ 50280
#define DM   768
#define NL   4
#define DS   16
#define DC   4
#define DTR  48
#define ROH  512
#define DI   1536
#define BB   2
#define LL   128
#define MM   (BB*LL)        // 256
#define FEATK (NL*DI*DS)    // 98304

// ---------------- scratch (device globals; no allocation allowed) ----------------
__device__ __align__(128) float g_x[MM*DM];
__device__ __align__(128) float g_xn[MM*DM];
__device__ __align__(128) float g_xz[MM*2*DI];
__device__ __align__(128) float g_xconv[MM*DI];
__device__ __align__(128) float g_dbc[MM*80];
__device__ __align__(128) float g_delta[MM*DI];
__device__ __align__(128) float g_y[MM*DI];
__device__ __align__(128) float g_feat[(size_t)MM*FEATK];   // ~100.7 MB
__device__ __align__(128) float g_h1[MM*ROH];
__device__ __align__(128) float g_h2[MM*(ROH/2)];
__device__ __align__(128) float g_xf[MM*DM];

// ---------------- tiny utility kernels ----------------
__global__ void zero_kernel(float* p, int n) {
    int i = blockIdx.x*256 + threadIdx.x;
    if (i < n) p[i] = 0.f;
}

__global__ void binit_kernel(float* p, const float* __restrict__ bias, int rows, int cols) {
    int i = blockIdx.x*256 + threadIdx.x;
    if (i < rows*cols) p[i] = bias[i % cols];
}

__global__ void embed_kernel(const int* __restrict__ ids, const float* __restrict__ emb,
                             float* __restrict__ x) {
    int i = blockIdx.x*256 + threadIdx.x;
    if (i >= MM*DM) return;
    int m = i / DM, j = i % DM;
    x[i] = emb[(size_t)ids[m]*DM + j];
}

__global__ void rmsnorm_kernel(const float* __restrict__ x, const float* __restrict__ w,
                               float* __restrict__ out) {
    int m = blockIdx.x;
    const float* xr = x + (size_t)m*DM;
    float s = 0.f;
    for (int j = threadIdx.x; j < DM; j += blockDim.x) { float v = xr[j]; s += v*v; }
    __shared__ float red[32];
    int lane = threadIdx.x & 31, wid = threadIdx.x >> 5;
    #pragma unroll
    for (int o = 16; o > 0; o >>= 1) s += __shfl_down_sync(0xffffffffu, s, o);
    if (lane == 0) red[wid] = s;
    __syncthreads();
    if (wid == 0) {
        s = (lane < (int)(blockDim.x >> 5)) ? red[lane] : 0.f;
        #pragma unroll
        for (int o = 16; o > 0; o >>= 1) s += __shfl_down_sync(0xffffffffu, s, o);
        if (lane == 0) red[0] = s;
    }
    __syncthreads();
    float inv = rsqrtf(red[0]/(float)DM + 1e-5f);
    for (int j = threadIdx.x; j < DM; j += blockDim.x)
        out[(size_t)m*DM + j] = xr[j]*inv*w[j];
}

// causal depthwise conv1d (kernel DC) + silu
__global__ void conv_kernel(const float* __restrict__ xz, const float* __restrict__ cw,
                            const float* __restrict__ cb, float* __restrict__ xconv) {
    int i = blockIdx.x*256 + threadIdx.x;
    if (i >= MM*DI) return;
    int d = i % DI, m = i / DI, t = m % LL, b = m / LL;
    float acc = cb[d];
    #pragma unroll
    for (int k = 0; k < DC; k++) {
        int tt = t + k - (DC-1);
        if (tt >= 0) acc += cw[d*DC + k] * xz[(size_t)(b*LL + tt)*(2*DI) + d];
    }
    xconv[i] = acc / (1.f + __expf(-acc));   // silu
}

// ---------------- generic tiled SGEMM ----------------
// C(M,N) (+)= A(M,K) * B(K,N).  NT=true: B given as (N,K) row-major (B^T access).
// flags: bit0 = relu applied to A on load, bit1 = atomicAdd into C (split-K)
#define GBM 128
#define GBN 64
#define GBK 16

template<bool NT>
__global__ void gemm_kernel(const float* __restrict__ A, const float* __restrict__ B,
                            float* __restrict__ C, int M, int N, int K,
                            int lda, int ldb, int ldc,
                            const float* __restrict__ bias, int flags, int kPerSplit) {
    __shared__ __align__(16) float As[GBK][GBM];
    __shared__ __align__(16) float Bs[GBK][GBN];
    const int tid = threadIdx.x;
    const int m0 = blockIdx.y * GBM;
    const int n0 = blockIdx.x * GBN;
    const int kb = blockIdx.z * kPerSplit;
    const int ke = min(K, kb + kPerSplit);
    const bool arelu = flags & 1;

    float acc[8][4];
    #pragma unroll
    for (int i = 0; i < 8; i++)
        #pragma unroll
        for (int j = 0; j < 4; j++) acc[i][j] = 0.f;

    const int ty = tid >> 4, tx = tid & 15;

    for (int k0 = kb; k0 < ke; k0 += GBK) {
        // ---- load A tile (128x16) as float4 along K, store transposed ----
        #pragma unroll
        for (int r = 0; r < 2; r++) {
            int q  = tid + r*256;        // 0..511 quads
            int m  = q >> 2;             // 0..127
            int kk = (q & 3) << 2;       // 0,4,8,12
            float4 v = make_float4(0.f, 0.f, 0.f, 0.f);
            if (m0 + m < M)
                v = *reinterpret_cast<const float4*>(A + (size_t)(m0+m)*lda + k0 + kk);
            if (arelu) { v.x = fmaxf(v.x,0.f); v.y = fmaxf(v.y,0.f);
                         v.z = fmaxf(v.z,0.f); v.w = fmaxf(v.w,0.f); }
            As[kk  ][m] = v.x; As[kk+1][m] = v.y; As[kk+2][m] = v.z; As[kk+3][m] = v.w;
        }
        // ---- load B tile (16x64) ----
        if (NT) {
            int q  = tid;                // 256 quads
            int n  = q >> 2;             // 0..63
            int kk = (q & 3) << 2;
            float4 v = make_float4(0.f, 0.f, 0.f, 0.f);
            if (n0 + n < N)
                v = *reinterpret_cast<const float4*>(B + (size_t)(n0+n)*ldb + k0 + kk);
            Bs[kk  ][n] = v.x; Bs[kk+1][n] = v.y; Bs[kk+2][n] = v.z; Bs[kk+3][n] = v.w;
        } else {
            #pragma unroll
            for (int i = 0; i < 4; i++) {
                int flat = i*256 + tid;
                int n = flat & 63;
                int k = flat >> 6;
                float v = 0.f;
                if (n0 + n < N) v = B[(size_t)(k0+k)*ldb + n0 + n];
                Bs[k][n] = v;
            }
        }
        __syncthreads();
        #pragma unroll
        for (int k = 0; k < GBK; k++) {
            float4 a0 = *reinterpret_cast<const float4*>(&As[k][ty*8]);
            float4 a1 = *reinterpret_cast<const float4*>(&As[k][ty*8 + 4]);
            float4 b4 = *reinterpret_cast<const float4*>(&Bs[k][tx*4]);
            float av[8] = {a0.x,a0.y,a0.z,a0.w,a1.x,a1.y,a1.z,a1.w};
            float bv[4] = {b4.x,b4.y,b4.z,b4.w};
            #pragma unroll
            for (int i = 0; i < 8; i++)
                #pragma unroll
                for (int j = 0; j < 4; j++) acc[i][j] += av[i]*bv[j];
        }
        __syncthreads();
    }
    #pragma unroll
    for (int i = 0; i < 8; i++) {
        int row = m0 + ty*8 + i;
        if (row >= M) continue;
        #pragma unroll
        for (int j = 0; j < 4; j++) {
            int col = n0 + tx*4 + j;
            if (col >= N) continue;
            float v = acc[i][j];
            if (flags & 2) atomicAdd(&C[(size_t)row*ldc + col], v);
            else { if (bias) v += bias[col]; C[(size_t)row*ldc + col] = v; }
        }
    }
}

// ---------------- selective scan ----------------
// block: 256 threads = 16 d-groups x 16 n-lanes; grid (DI/16, B)
// fuses: softplus(delta), dA=exp(delta*A), recurrence, hs writes (both layouts),
//        y = (sum_n h*C + D*xconv) * silu(z)
__global__ void scan_kernel(const float* __restrict__ dbc,    // (M,80): [dt|Bm|Cm]
                            const float* __restrict__ draw,   // (M,DI) pre-softplus
                            const float* __restrict__ xconv,  // (M,DI)
                            const float* __restrict__ xz,     // (M,2*DI) (z half)
                            const float* __restrict__ A_log_l,// (DI,DS)
                            const float* __restrict__ Dp_l,   // (DI)
                            float* __restrict__ y,            // (M,DI)
                            float* __restrict__ hid,          // per-layer: (B,L,DI,DS)
                            float* __restrict__ feat,         // (M, FEATK)
                            int layer) {
    int n  = threadIdx.x & 15;
    int dl = threadIdx.x >> 4;
    int d  = blockIdx.x*16 + dl;
    int b  = blockIdx.y;
    float a  = -__expf(A_log_l[d*DS + n]);
    float Dv = Dp_l[d];
    float h = 0.f;
    for (int t = 0; t < LL; t++) {
        int m = b*LL + t;
        float dr = draw[m*DI + d];
        float delta = (dr > 20.f) ? dr : log1pf(__expf(dr));
        float xc = xconv[m*DI + d];
        float Bv = dbc[m*80 + DTR + n];
        float Cv = dbc[m*80 + DTR + DS + n];
        float dA = __expf(delta * a);
        h = fmaf(dA, h, delta*Bv*xc);
        size_t ho = (size_t)m*DI*DS + (size_t)d*DS + n;
        hid[ho] = h;
        feat[(size_t)m*FEATK + (size_t)layer*DI*DS + d*DS + n] = h;
        float p = h * Cv;
        p += __shfl_down_sync(0xffffffffu, p, 8, 16);
        p += __shfl_down_sync(0xffffffffu, p, 4, 16);
        p += __shfl_down_sync(0xffffffffu, p, 2, 16);
        p += __shfl_down_sync(0xffffffffu, p, 1, 16);
        if (n == 0) {
            float z = xz[(size_t)m*(2*DI) + DI + d];
            float sz = z / (1.f + __expf(-z));
            y[m*DI + d] = (p + Dv*xc) * sz;
        }
    }
}

// ---------------- launcher ----------------
extern "C" void kernel_launch(void* const* d_in, const int* in_sizes, int n_in,
                              void* d_out, int out_size) {
    const int*   ids        = (const int*)  d_in[0];
    const float* emb        = (const float*)d_in[1];
    const float* norm_f     = (const float*)d_in[2];
    const float* norm_w     = (const float*)d_in[3];
    const float* in_proj_w  = (const float*)d_in[4];
    const float* conv_w     = (const float*)d_in[5];
    const float* conv_b     = (const float*)d_in[6];
    const float* x_proj_w   = (const float*)d_in[7];
    const float* dt_w       = (const float*)d_in[8];
    const float* dt_b       = (const float*)d_in[9];
    const float* A_log      = (const float*)d_in[10];
    const float* Dp         = (const float*)d_in[11];
    const float* out_proj_w = (const float*)d_in[12];
    const float* ro_w1      = (const float*)d_in[13];
    const float* ro_b1      = (const float*)d_in[14];
    const float* ro_w2      = (const float*)d_in[15];
    const float* ro_b2      = (const float*)d_in[16];
    const float* ro_w3      = (const float*)d_in[17];
    const float* ro_b3      = (const float*)d_in[18];

    float* out      = (float*)d_out;
    float* out_main = out;
    float* out_ro   = out + (size_t)BB*LL*V_SZ;
    float* out_hid  = out_ro + (size_t)BB*LL*V_SZ;

    float *px, *pxn, *pxz, *pxconv, *pdbc, *pdelta, *py, *pfeat, *ph1, *ph2, *pxf;
    cudaGetSymbolAddress((void**)&px,     g_x);
    cudaGetSymbolAddress((void**)&pxn,    g_xn);
    cudaGetSymbolAddress((void**)&pxz,    g_xz);
    cudaGetSymbolAddress((void**)&pxconv, g_xconv);
    cudaGetSymbolAddress((void**)&pdbc,   g_dbc);
    cudaGetSymbolAddress((void**)&pdelta, g_delta);
    cudaGetSymbolAddress((void**)&py,     g_y);
    cudaGetSymbolAddress((void**)&pfeat,  g_feat);
    cudaGetSymbolAddress((void**)&ph1,    g_h1);
    cudaGetSymbolAddress((void**)&ph2,    g_h2);
    cudaGetSymbolAddress((void**)&pxf,    g_xf);

    embed_kernel<<<(MM*DM + 255)/256, 256>>>(ids, emb, px);

    for (int l = 0; l < NL; l++) {
        rmsnorm_kernel<<<MM, 256>>>(px, norm_w + (size_t)l*DM, pxn);

        // xz = xn @ in_proj  (split-K=2, atomic into zeroed buffer)
        zero_kernel<<<(MM*2*DI + 255)/256, 256>>>(pxz, MM*2*DI);
        gemm_kernel<false><<<dim3(48, 2, 2), 256>>>(
            pxn, in_proj_w + (size_t)l*DM*2*DI, pxz,
            MM, 2*DI, DM, DM, 2*DI, 2*DI, nullptr, 2, 384);

        conv_kernel<<<(MM*DI + 255)/256, 256>>>(
            pxz, conv_w + (size_t)l*DI*DC, conv_b + (size_t)l*DI, pxconv);

        // dbc = xconv @ x_proj  (split-K=16)
        zero_kernel<<<(MM*80 + 255)/256, 256>>>(pdbc, MM*80);
        gemm_kernel<false><<<dim3(2, 2, 16), 256>>>(
            pxconv, x_proj_w + (size_t)l*DI*80, pdbc,
            MM, 80, DI, DI, 80, 80, nullptr, 2, 96);

        // delta_pre = dt @ dt_w + dt_b  (split-K=3, bias pre-init)
        binit_kernel<<<(MM*DI + 255)/256, 256>>>(pdelta, dt_b + (size_t)l*DI, MM, DI);
        gemm_kernel<false><<<dim3(24, 2, 3), 256>>>(
            pdbc, dt_w + (size_t)l*DTR*DI, pdelta,
            MM, DI, DTR, 80, DI, DI, nullptr, 2, 16);

        scan_kernel<<<dim3(DI/16, BB), 256>>>(
            pdbc, pdelta, pxconv, pxz,
            A_log + (size_t)l*DI*DS, Dp + (size_t)l*DI,
            py, out_hid + (size_t)l*BB*LL*DI*DS, pfeat, l);

        // x += y @ out_proj  (split-K=8, atomic residual add directly into x)
        gemm_kernel<false><<<dim3(12, 2, 8), 256>>>(
            py, out_proj_w + (size_t)l*DI*DM, px,
            MM, DM, DI, DI, DM, DM, nullptr, 2, 192);
    }

    // final norm + tied lm head (NT gemm against embed)
    rmsnorm_kernel<<<MM, 256>>>(px, norm_f, pxf);
    gemm_kernel<true><<<dim3((V_SZ + 63)/64, 2, 1), 256>>>(
        pxf, emb, out_main, MM, V_SZ, DM, DM, DM, V_SZ, nullptr, 0, DM);

    // readout MLP
    binit_kernel<<<(MM*ROH + 255)/256, 256>>>(ph1, ro_b1, MM, ROH);
    gemm_kernel<false><<<dim3(8, 2, 48), 256>>>(
        pfeat, ro_w1, ph1, MM, ROH, FEATK, FEATK, ROH, ROH, nullptr, 2, 2048);

    binit_kernel<<<(MM*(ROH/2) + 255)/256, 256>>>(ph2, ro_b2, MM, ROH/2);
    gemm_kernel<false><<<dim3(4, 2, 8), 256>>>(
        ph1, ro_w2, ph2, MM, ROH/2, ROH, ROH, ROH/2, ROH/2, nullptr, 3, 64);  // relu(A), atomic

    gemm_kernel<false><<<dim3((V_SZ + 63)/64, 2, 1), 256>>>(
        ph2, ro_w3, out_ro, MM, V_SZ, ROH/2, ROH/2, V_SZ, V_SZ, ro_b3, 1, ROH/2); // relu(A), bias
}

// round 3
// speedup vs baseline: 1.5484x; 1.5484x over previous
#include <cuda_runtime.h>
#include <cuda_bf16.h>
#include <math.h>
#include <stdint.h>

#define V_SZ 50280
#define DM   768
#define NL   4
#define DS   16
#define DC   4
#define DTR  48
#define ROH  512
#define DI   1536
#define BB   2
#define LL   128
#define MM   (BB*LL)        // 256
#define LBLK (DI*DS)        // 24576 per-layer feature block

// ---------------- scratch (device globals; no allocation allowed) ----------------
__device__ __align__(128) float g_x[MM*DM];
__device__ __align__(128) float g_xn[MM*DM];
__device__ __align__(128) float g_xz[MM*2*DI];
__device__ __align__(128) float g_xconv[MM*DI];
__device__ __align__(128) float g_dbc[MM*80];
__device__ __align__(128) float g_delta[MM*DI];
__device__ __align__(128) float g_y[MM*DI];
__device__ __align__(128) float g_h1[MM*ROH];
__device__ __align__(128) float g_h2[MM*(ROH/2)];
__device__ __align__(128) float g_xf[MM*DM];

// ---------------- helpers ----------------
__device__ __forceinline__ uint32_t smem_u32(const void* p) {
    uint32_t a;
    asm("{ .reg .u64 t; cvta.to.shared.u64 t, %1; cvt.u32.u64 %0, t; }" : "=r"(a) : "l"(p));
    return a;
}
__device__ __forceinline__ uint32_t pack_bf2(float a, float b) {
    __nv_bfloat162 t = __floats2bfloat162_rn(a, b);
    return *reinterpret_cast<uint32_t*>(&t);
}
__device__ __forceinline__ void split2(float a, float b, uint32_t& hi, uint32_t& lo) {
    float ah = __bfloat162float(__float2bfloat16(a));
    float bh = __bfloat162float(__float2bfloat16(b));
    hi = pack_bf2(ah, bh);
    lo = pack_bf2(a - ah, b - bh);
}
__device__ __forceinline__ void ldsm_x4(uint32_t* r, uint32_t addr) {
    asm volatile("ldmatrix.sync.aligned.m8n8.x4.shared.b16 {%0,%1,%2,%3}, [%4];"
        : "=r"(r[0]), "=r"(r[1]), "=r"(r[2]), "=r"(r[3]) : "r"(addr));
}
__device__ __forceinline__ void mma16816(float* c, const uint32_t* a, const uint32_t* b) {
    asm volatile(
        "mma.sync.aligned.m16n8k16.row.col.f32.bf16.bf16.f32 "
        "{%0,%1,%2,%3}, {%4,%5,%6,%7}, {%8,%9}, {%0,%1,%2,%3};"
        : "+f"(c[0]), "+f"(c[1]), "+f"(c[2]), "+f"(c[3])
        : "r"(a[0]), "r"(a[1]), "r"(a[2]), "r"(a[3]), "r"(b[0]), "r"(b[1]));
}

// ================= HMMA bf16x3 GEMM =================
// C(256,N) (+)= A(256,K) * B.  BSRC: 0 -> B is (K,N) row-major; 1 -> B is (N,K) row-major.
// ALAYERED: A is out_hid layout (NL, 256, LBLK) viewed as (256, NL*LBLK).
// flags: bit0 relu(A), bit1 atomicAdd epilogue.
// Tiles: BM=256 (full M), BN=64, BK=32. 8 warps, each 32(m) x 64(n).
#define ASTR     112                 // bytes per smem row (16B aligned, conflict-free)
#define OFF_ALO  28672               // 256*112
#define OFF_BHI  57344
#define OFF_BLO  64512               // +64*112
#define MMSTAGE  71680
#define MM_DSM   (2*MMSTAGE)

template<int BSRC, int ALAYERED>
__global__ __launch_bounds__(256, 1)
void mm_gemm(const float* __restrict__ A, int lda,
             const float* __restrict__ B, int ldb,
             float* __restrict__ C, int ldc,
             int N, int kPerSplit,
             const float* __restrict__ bias, int flags) {
    extern __shared__ char smem[];
    const uint32_t sbase0 = smem_u32(smem);
    const int tid = threadIdx.x, lid = tid & 31, wid = tid >> 5;
    const int n0 = blockIdx.x * 64;
    const int kb = blockIdx.y * kPerSplit;
    const int nch = kPerSplit >> 5;
    const bool arelu = flags & 1;

    float acc[2][8][4];
    #pragma unroll
    for (int i = 0; i < 2; i++)
        #pragma unroll
        for (int j = 0; j < 8; j++)
            #pragma unroll
            for (int k = 0; k < 4; k++) acc[i][j][k] = 0.f;

    float4 avr[8];                    // A staging: 256x32 / 256 thr = 8 float4
    float4 bqr[2];                    // B staging (BSRC=1)
    float  bsr[8];                    // B staging (BSRC=0)

    auto loadG = [&](int ic) {
        int k0b = kb + (ic << 5);
        const float* Ae = A;
        int k0 = k0b;
        if (ALAYERED) {
            int l = k0b / LBLK;
            Ae = A + (size_t)l * MM * LBLK;
            k0 = k0b - l * LBLK;
        }
        #pragma unroll
        for (int it = 0; it < 8; it++) {
            int idx = it * 256 + tid;
            int row = idx >> 3, kq = idx & 7;
            avr[it] = *(const float4*)(Ae + (size_t)row * lda + k0 + (kq << 2));
        }
        if (BSRC == 0) {
            #pragma unroll
            for (int it = 0; it < 8; it++) {
                int idx = it * 256 + tid;
                int n = idx & 63, kk = idx >> 6;
                bsr[it] = (n0 + n < N) ? B[(size_t)(k0b + kk) * ldb + n0 + n] : 0.f;
            }
        } else {
            #pragma unroll
            for (int it = 0; it < 2; it++) {
                int idx = it * 256 + tid;
                int n = idx >> 3, kq = idx & 7;
                bqr[it] = (n0 + n < N)
                    ? *(const float4*)(B + (size_t)(n0 + n) * ldb + k0b + (kq << 2))
                    : make_float4(0.f, 0.f, 0.f, 0.f);
            }
        }
    };
    auto storeS = [&](int buf) {
        char* sp = smem + buf * MMSTAGE;
        #pragma unroll
        for (int it = 0; it < 8; it++) {
            int idx = it * 256 + tid;
            int row = idx >> 3, kq = idx & 7;
            float4 v = avr[it];
            if (arelu) { v.x = fmaxf(v.x, 0.f); v.y = fmaxf(v.y, 0.f);
                         v.z = fmaxf(v.z, 0.f); v.w = fmaxf(v.w, 0.f); }
            uint32_t h0, l0, h1, l1;
            split2(v.x, v.y, h0, l0);
            split2(v.z, v.w, h1, l1);
            uint32_t off = row * ASTR + (kq << 3);
            *(uint32_t*)(sp + off)               = h0;
            *(uint32_t*)(sp + off + 4)           = h1;
            *(uint32_t*)(sp + OFF_ALO + off)     = l0;
            *(uint32_t*)(sp + OFF_ALO + off + 4) = l1;
        }
        if (BSRC == 0) {
            #pragma unroll
            for (int it = 0; it < 8; it++) {
                int idx = it * 256 + tid;
                int n = idx & 63, kk = idx >> 6;
                float f  = bsr[it];
                float fh = __bfloat162float(__float2bfloat16(f));
                uint32_t off = n * ASTR + (kk << 1);
                *(__nv_bfloat16*)(sp + OFF_BHI + off) = __float2bfloat16(f);
                *(__nv_bfloat16*)(sp + OFF_BLO + off) = __float2bfloat16(f - fh);
            }
        } else {
            #pragma unroll
            for (int it = 0; it < 2; it++) {
                int idx = it * 256 + tid;
                int n = idx >> 3, kq = idx & 7;
                float4 v = bqr[it];
                uint32_t h0, l0, h1, l1;
                split2(v.x, v.y, h0, l0);
                split2(v.z, v.w, h1, l1);
                uint32_t off = n * ASTR + (kq << 3);
                *(uint32_t*)(sp + OFF_BHI + off)     = h0;
                *(uint32_t*)(sp + OFF_BHI + off + 4) = h1;
                *(uint32_t*)(sp + OFF_BLO + off)     = l0;
                *(uint32_t*)(sp + OFF_BLO + off + 4) = l1;
            }
        }
    };
    auto compute = [&](int buf) {
        const uint32_t sb = sbase0 + buf * MMSTAGE;
        #pragma unroll
        for (int k16 = 0; k16 < 2; k16++) {
            uint32_t ahi[2][4], alo[2][4];
            #pragma unroll
            for (int mt = 0; mt < 2; mt++) {
                uint32_t aoff = (wid * 32 + mt * 16 + (lid & 15)) * ASTR
                              + (k16 << 5) + ((lid >> 4) << 4);
                ldsm_x4(ahi[mt], sb + aoff);
                ldsm_x4(alo[mt], sb + OFF_ALO + aoff);
            }
            #pragma unroll
            for (int nh = 0; nh < 4; nh++) {
                uint32_t bhi4[4], blo4[4];
                uint32_t boff = (nh * 16 + (lid & 7) + ((lid >> 4) << 3)) * ASTR
                              + (k16 << 5) + (((lid >> 3) & 1) << 4);
                ldsm_x4(bhi4, sb + OFF_BHI + boff);
                ldsm_x4(blo4, sb + OFF_BLO + boff);
                #pragma unroll
                for (int mt = 0; mt < 2; mt++)
                    #pragma unroll
                    for (int j = 0; j < 2; j++) {
                        int nt = nh * 2 + j;
                        mma16816(acc[mt][nt], ahi[mt], &bhi4[j * 2]);
                        mma16816(acc[mt][nt], ahi[mt], &blo4[j * 2]);
                        mma16816(acc[mt][nt], alo[mt], &bhi4[j * 2]);
                    }
            }
        }
    };

    loadG(0);
    storeS(0);
    __syncthreads();
    for (int ic = 0; ic < nch; ic++) {
        if (ic + 1 < nch) loadG(ic + 1);
        compute(ic & 1);
        __syncthreads();
        if (ic + 1 < nch) { storeS((ic + 1) & 1); __syncthreads(); }
    }

    // epilogue
    #pragma unroll
    for (int mt = 0; mt < 2; mt++) {
        int r0 = wid * 32 + mt * 16 + (lid >> 2);
        #pragma unroll
        for (int nt = 0; nt < 8; nt++) {
            int col = n0 + nt * 8 + ((lid & 3) << 1);
            float* c = acc[mt][nt];
            if (flags & 2) {
                if (col < N) {
                    atomicAdd(&C[(size_t)r0 * ldc + col], c[0]);
                    atomicAdd(&C[(size_t)(r0 + 8) * ldc + col], c[2]);
                }
                if (col + 1 < N) {
                    atomicAdd(&C[(size_t)r0 * ldc + col + 1], c[1]);
                    atomicAdd(&C[(size_t)(r0 + 8) * ldc + col + 1], c[3]);
                }
            } else {
                if (col < N) {
                    float b0 = bias ? bias[col] : 0.f;
                    C[(size_t)r0 * ldc + col]       = c[0] + b0;
                    C[(size_t)(r0 + 8) * ldc + col] = c[2] + b0;
                }
                if (col + 1 < N) {
                    float b1 = bias ? bias[col + 1] : 0.f;
                    C[(size_t)r0 * ldc + col + 1]       = c[1] + b1;
                    C[(size_t)(r0 + 8) * ldc + col + 1] = c[3] + b1;
                }
            }
        }
    }
}

// ---------------- tiny utility kernels ----------------
__global__ void zero_kernel(float* p, int n) {
    int i = blockIdx.x*256 + threadIdx.x;
    if (i < n) p[i] = 0.f;
}
__global__ void binit_kernel(float* p, const float* __restrict__ bias, int rows, int cols) {
    int i = blockIdx.x*256 + threadIdx.x;
    if (i < rows*cols) p[i] = bias[i % cols];
}
__global__ void embed_kernel(const int* __restrict__ ids, const float* __restrict__ emb,
                             float* __restrict__ x) {
    int i = blockIdx.x*256 + threadIdx.x;
    if (i >= MM*DM) return;
    int m = i / DM, j = i % DM;
    x[i] = emb[(size_t)ids[m]*DM + j];
}
__global__ void rmsnorm_kernel(const float* __restrict__ x, const float* __restrict__ w,
                               float* __restrict__ out) {
    int m = blockIdx.x;
    const float* xr = x + (size_t)m*DM;
    float s = 0.f;
    for (int j = threadIdx.x; j < DM; j += blockDim.x) { float v = xr[j]; s += v*v; }
    __shared__ float red[32];
    int lane = threadIdx.x & 31, wid = threadIdx.x >> 5;
    #pragma unroll
    for (int o = 16; o > 0; o >>= 1) s += __shfl_down_sync(0xffffffffu, s, o);
    if (lane == 0) red[wid] = s;
    __syncthreads();
    if (wid == 0) {
        s = (lane < (int)(blockDim.x >> 5)) ? red[lane] : 0.f;
        #pragma unroll
        for (int o = 16; o > 0; o >>= 1) s += __shfl_down_sync(0xffffffffu, s, o);
        if (lane == 0) red[0] = s;
    }
    __syncthreads();
    float inv = rsqrtf(red[0]/(float)DM + 1e-5f);
    for (int j = threadIdx.x; j < DM; j += blockDim.x)
        out[(size_t)m*DM + j] = xr[j]*inv*w[j];
}
__global__ void conv_kernel(const float* __restrict__ xz, const float* __restrict__ cw,
                            const float* __restrict__ cb, float* __restrict__ xconv) {
    int i = blockIdx.x*256 + threadIdx.x;
    if (i >= MM*DI) return;
    int d = i % DI, m = i / DI, t = m % LL, b = m / LL;
    float acc = cb[d];
    #pragma unroll
    for (int k = 0; k < DC; k++) {
        int tt = t + k - (DC-1);
        if (tt >= 0) acc += cw[d*DC + k] * xz[(size_t)(b*LL + tt)*(2*DI) + d];
    }
    xconv[i] = acc / (1.f + __expf(-acc));   // silu
}

// ---------------- small FFMA GEMM (tiny shapes) ----------------
#define GBM 128
#define GBN 64
#define GBK 16
__global__ void gemm_kernel(const float* __restrict__ A, const float* __restrict__ B,
                            float* __restrict__ C, int M, int N, int K,
                            int lda, int ldb, int ldc,
                            const float* __restrict__ bias, int flags, int kPerSplit) {
    __shared__ __align__(16) float As[GBK][GBM];
    __shared__ __align__(16) float Bs[GBK][GBN];
    const int tid = threadIdx.x;
    const int m0 = blockIdx.y * GBM;
    const int n0 = blockIdx.x * GBN;
    const int kb = blockIdx.z * kPerSplit;
    const int ke = min(K, kb + kPerSplit);
    const bool arelu = flags & 1;
    float acc[8][4];
    #pragma unroll
    for (int i = 0; i < 8; i++)
        #pragma unroll
        for (int j = 0; j < 4; j++) acc[i][j] = 0.f;
    const int ty = tid >> 4, tx = tid & 15;
    for (int k0 = kb; k0 < ke; k0 += GBK) {
        #pragma unroll
        for (int r = 0; r < 2; r++) {
            int q  = tid + r*256;
            int m  = q >> 2;
            int kk = (q & 3) << 2;
            float4 v = make_float4(0.f, 0.f, 0.f, 0.f);
            if (m0 + m < M)
                v = *reinterpret_cast<const float4*>(A + (size_t)(m0+m)*lda + k0 + kk);
            if (arelu) { v.x = fmaxf(v.x,0.f); v.y = fmaxf(v.y,0.f);
                         v.z = fmaxf(v.z,0.f); v.w = fmaxf(v.w,0.f); }
            As[kk  ][m] = v.x; As[kk+1][m] = v.y; As[kk+2][m] = v.z; As[kk+3][m] = v.w;
        }
        #pragma unroll
        for (int i = 0; i < 4; i++) {
            int flat = i*256 + tid;
            int n = flat & 63;
            int k = flat >> 6;
            float v = 0.f;
            if (n0 + n < N) v = B[(size_t)(k0+k)*ldb + n0 + n];
            Bs[k][n] = v;
        }
        __syncthreads();
        #pragma unroll
        for (int k = 0; k < GBK; k++) {
            float4 a0 = *reinterpret_cast<const float4*>(&As[k][ty*8]);
            float4 a1 = *reinterpret_cast<const float4*>(&As[k][ty*8 + 4]);
            float4 b4 = *reinterpret_cast<const float4*>(&Bs[k][tx*4]);
            float av[8] = {a0.x,a0.y,a0.z,a0.w,a1.x,a1.y,a1.z,a1.w};
            float bv[4] = {b4.x,b4.y,b4.z,b4.w};
            #pragma unroll
            for (int i = 0; i < 8; i++)
                #pragma unroll
                for (int j = 0; j < 4; j++) acc[i][j] += av[i]*bv[j];
        }
        __syncthreads();
    }
    #pragma unroll
    for (int i = 0; i < 8; i++) {
        int row = m0 + ty*8 + i;
        if (row >= M) continue;
        #pragma unroll
        for (int j = 0; j < 4; j++) {
            int col = n0 + tx*4 + j;
            if (col >= N) continue;
            float v = acc[i][j];
            if (flags & 2) atomicAdd(&C[(size_t)row*ldc + col], v);
            else { if (bias) v += bias[col]; C[(size_t)row*ldc + col] = v; }
        }
    }
}

// ---------------- selective scan ----------------
__global__ void scan_kernel(const float* __restrict__ dbc,
                            const float* __restrict__ draw,
                            const float* __restrict__ xconv,
                            const float* __restrict__ xz,
                            const float* __restrict__ A_log_l,
                            const float* __restrict__ Dp_l,
                            float* __restrict__ y,
                            float* __restrict__ hid) {
    int n  = threadIdx.x & 15;
    int dl = threadIdx.x >> 4;
    int d  = blockIdx.x*16 + dl;
    int b  = blockIdx.y;
    float a  = -__expf(A_log_l[d*DS + n]);
    float Dv = Dp_l[d];
    float h = 0.f;
    for (int t = 0; t < LL; t++) {
        int m = b*LL + t;
        float dr = draw[m*DI + d];
        float delta = (dr > 20.f) ? dr : log1pf(__expf(dr));
        float xc = xconv[m*DI + d];
        float Bv = dbc[m*80 + DTR + n];
        float Cv = dbc[m*80 + DTR + DS + n];
        float dA = __expf(delta * a);
        h = fmaf(dA, h, delta*Bv*xc);
        hid[(size_t)m*LBLK + (size_t)d*DS + n] = h;
        float p = h * Cv;
        p += __shfl_down_sync(0xffffffffu, p, 8, 16);
        p += __shfl_down_sync(0xffffffffu, p, 4, 16);
        p += __shfl_down_sync(0xffffffffu, p, 2, 16);
        p += __shfl_down_sync(0xffffffffu, p, 1, 16);
        if (n == 0) {
            float z = xz[(size_t)m*(2*DI) + DI + d];
            float sz = z / (1.f + __expf(-z));
            y[m*DI + d] = (p + Dv*xc) * sz;
        }
    }
}

// ---------------- launcher ----------------
extern "C" void kernel_launch(void* const* d_in, const int* in_sizes, int n_in,
                              void* d_out, int out_size) {
    const int*   ids        = (const int*)  d_in[0];
    const float* emb        = (const float*)d_in[1];
    const float* norm_f     = (const float*)d_in[2];
    const float* norm_w     = (const float*)d_in[3];
    const float* in_proj_w  = (const float*)d_in[4];
    const float* conv_w     = (const float*)d_in[5];
    const float* conv_b     = (const float*)d_in[6];
    const float* x_proj_w   = (const float*)d_in[7];
    const float* dt_w       = (const float*)d_in[8];
    const float* dt_b       = (const float*)d_in[9];
    const float* A_log      = (const float*)d_in[10];
    const float* Dp         = (const float*)d_in[11];
    const float* out_proj_w = (const float*)d_in[12];
    const float* ro_w1      = (const float*)d_in[13];
    const float* ro_b1      = (const float*)d_in[14];
    const float* ro_w2      = (const float*)d_in[15];
    const float* ro_b2      = (const float*)d_in[16];
    const float* ro_w3      = (const float*)d_in[17];
    const float* ro_b3      = (const float*)d_in[18];

    float* out      = (float*)d_out;
    float* out_main = out;
    float* out_ro   = out + (size_t)BB*LL*V_SZ;
    float* out_hid  = out_ro + (size_t)BB*LL*V_SZ;

    float *px, *pxn, *pxz, *pxconv, *pdbc, *pdelta, *py, *ph1, *ph2, *pxf;
    cudaGetSymbolAddress((void**)&px,     g_x);
    cudaGetSymbolAddress((void**)&pxn,    g_xn);
    cudaGetSymbolAddress((void**)&pxz,    g_xz);
    cudaGetSymbolAddress((void**)&pxconv, g_xconv);
    cudaGetSymbolAddress((void**)&pdbc,   g_dbc);
    cudaGetSymbolAddress((void**)&pdelta, g_delta);
    cudaGetSymbolAddress((void**)&py,     g_y);
    cudaGetSymbolAddress((void**)&ph1,    g_h1);
    cudaGetSymbolAddress((void**)&ph2,    g_h2);
    cudaGetSymbolAddress((void**)&pxf,    g_xf);

    cudaFuncSetAttribute(mm_gemm<0,0>, cudaFuncAttributeMaxDynamicSharedMemorySize, MM_DSM);
    cudaFuncSetAttribute(mm_gemm<1,0>, cudaFuncAttributeMaxDynamicSharedMemorySize, MM_DSM);
    cudaFuncSetAttribute(mm_gemm<0,1>, cudaFuncAttributeMaxDynamicSharedMemorySize, MM_DSM);

    embed_kernel<<<(MM*DM + 255)/256, 256>>>(ids, emb, px);

    for (int l = 0; l < NL; l++) {
        rmsnorm_kernel<<<MM, 256>>>(px, norm_w + (size_t)l*DM, pxn);

        // xz = xn @ in_proj   (HMMA, split-K=4 into zeroed buffer)
        zero_kernel<<<(MM*2*DI + 255)/256, 256>>>(pxz, MM*2*DI);
        mm_gemm<0,0><<<dim3(48, 4), 256, MM_DSM>>>(
            pxn, DM, in_proj_w + (size_t)l*DM*2*DI, 2*DI, pxz, 2*DI,
            2*DI, 192, nullptr, 2);

        conv_kernel<<<(MM*DI + 255)/256, 256>>>(
            pxz, conv_w + (size_t)l*DI*DC, conv_b + (size_t)l*DI, pxconv);

        // dbc = xconv @ x_proj  (tiny: FFMA split-K=16)
        zero_kernel<<<(MM*80 + 255)/256, 256>>>(pdbc, MM*80);
        gemm_kernel<<<dim3(2, 2, 16), 256>>>(
            pxconv, x_proj_w + (size_t)l*DI*80, pdbc,
            MM, 80, DI, DI, 80, 80, nullptr, 2, 96);

        // delta_pre = dt @ dt_w + dt_b  (tiny: FFMA split-K=3, bias pre-init)
        binit_kernel<<<(MM*DI + 255)/256, 256>>>(pdelta, dt_b + (size_t)l*DI, MM, DI);
        gemm_kernel<<<dim3(24, 2, 3), 256>>>(
            pdbc, dt_w + (size_t)l*DTR*DI, pdelta,
            MM, DI, DTR, 80, DI, DI, nullptr, 2, 16);

        scan_kernel<<<dim3(DI/16, BB), 256>>>(
            pdbc, pdelta, pxconv, pxz,
            A_log + (size_t)l*DI*DS, Dp + (size_t)l*DI,
            py, out_hid + (size_t)l*MM*LBLK);

        // x += y @ out_proj   (HMMA, split-K=12, atomic residual into x)
        mm_gemm<0,0><<<dim3(12, 12), 256, MM_DSM>>>(
            py, DI, out_proj_w + (size_t)l*DI*DM, DM, px, DM,
            DM, 128, nullptr, 2);
    }

    // final norm + tied lm head (B = embed (V, DM) = (N, K) row-major)
    rmsnorm_kernel<<<MM, 256>>>(px, norm_f, pxf);
    mm_gemm<1,0><<<dim3((V_SZ + 63)/64, 1), 256, MM_DSM>>>(
        pxf, DM, emb, DM, out_main, V_SZ,
        V_SZ, DM, nullptr, 0);

    // readout MLP: h1 = feat @ ro_w1 + b1; feat read directly from out_hid (layered A)
    binit_kernel<<<(MM*ROH + 255)/256, 256>>>(ph1, ro_b1, MM, ROH);
    mm_gemm<0,1><<<dim3(8, 24), 256, MM_DSM>>>(
        out_hid, LBLK, ro_w1, ROH, ph1, ROH,
        ROH, 4096, nullptr, 2);

    // h2 = relu(h1) @ ro_w2 + b2  (tiny: FFMA, relu(A), atomic into bias-init)
    binit_kernel<<<(MM*(ROH/2) + 255)/256, 256>>>(ph2, ro_b2, MM, ROH/2);
    gemm_kernel<<<dim3(4, 2, 8), 256>>>(
        ph1, ro_w2, ph2, MM, ROH/2, ROH, ROH, ROH/2, ROH/2, nullptr, 3, 64);

    // readout_logits = relu(h2) @ ro_w3 + b3  (HMMA, relu(A), bias store)
    mm_gemm<0,0><<<dim3((V_SZ + 63)/64, 1), 256, MM_DSM>>>(
        ph2, ROH/2, ro_w3, V_SZ, out_ro, V_SZ,
        V_SZ, ROH/2, ro_b3, 1);
}